// round 7
// baseline (speedup 1.0000x reference)
#include <cuda_runtime.h>
#include <cuda_fp16.h>
#include <float.h>

#define NIMG 32
#define H    512
#define W    512
#define HW   (H * W)
#define CHW  (3 * HW)

#define NEG2 0xFC00FC00u      // half2(-inf, -inf)

#define SR    16                     // vpass output rows per strip
#define VBLK  (NIMG * 32)            // 1024 blocks

__device__ __half g_hmax[NIMG * HW]; // fp16 intermediate (16.75 MB, L2-resident)
__device__ float  g_partial[VBLK];
__device__ int    g_count;           // zero-init; reset by last block

__device__ __forceinline__ unsigned hmax2u(unsigned a, unsigned b) {
    __half2 ha = *reinterpret_cast<__half2*>(&a);
    __half2 hb = *reinterpret_cast<__half2*>(&b);
    __half2 hm = __hmax2(ha, hb);
    return *reinterpret_cast<unsigned*>(&hm);
}
__device__ __forceinline__ unsigned sh1(unsigned a, unsigned b) {
    return __byte_perm(a, b, 0x5432);   // (a.hi, b.lo)
}

// ---------------------------------------------------------------------------
// Kernel 1 (unchanged, measured 21.5us @ 62% DRAM):
// c = 1 - min3(channels) -> fp16, horizontal 35-wide sliding max, packed half2.
// ---------------------------------------------------------------------------
__global__ __launch_bounds__(128) void hpass_kernel(const float* __restrict__ img) {
    const int row = blockIdx.x;
    const int n   = row >> 9;
    const int h   = row & (H - 1);
    const float* p = img + (size_t)n * CHW + (size_t)h * W;

    __shared__ unsigned s2[276];   // px -20 .. 531
    __shared__ unsigned t2[276];

    const int tid = threadIdx.x;

    if (tid < 20) s2[tid < 10 ? tid : 256 + tid] = NEG2;

    const float4 a = ((const float4*)p)[tid];
    const float4 b = ((const float4*)(p + HW))[tid];
    const float4 c = ((const float4*)(p + 2 * HW))[tid];
    float c0 = 1.0f - fminf(a.x, fminf(b.x, c.x));
    float c1 = 1.0f - fminf(a.y, fminf(b.y, c.y));
    float c2 = 1.0f - fminf(a.z, fminf(b.z, c.z));
    float c3 = 1.0f - fminf(a.w, fminf(b.w, c.w));
    __half2 h01 = __floats2half2_rn(c0, c1);
    __half2 h23 = __floats2half2_rn(c2, c3);
    s2[2 * tid + 10] = *reinterpret_cast<unsigned*>(&h01);
    s2[2 * tid + 11] = *reinterpret_cast<unsigned*>(&h23);
    __syncthreads();

    #pragma unroll
    for (int i = tid; i < 273; i += 128) {
        const unsigned A = s2[i], B = s2[i + 1], C = s2[i + 2];
        t2[i] = hmax2u(hmax2u(hmax2u(A, sh1(A, B)), hmax2u(B, sh1(B, C))), C);
    }
    __syncthreads();

    unsigned* orow = (unsigned*)(g_hmax + (size_t)row * W);
    #pragma unroll
    for (int q = tid; q < 256; q += 128) {
        unsigned v;
        v = sh1(t2[q + 1], t2[q + 2]);
        v = hmax2u(v, t2[q + 4]);
        v = hmax2u(v, sh1(t2[q + 6], t2[q + 7]));
        v = hmax2u(v, t2[q + 9]);
        v = hmax2u(v, sh1(t2[q + 11], t2[q + 12]));
        v = hmax2u(v, t2[q + 14]);
        v = hmax2u(v, sh1(t2[q + 16], t2[q + 17]));
        orow[q] = v;
    }
}

// ---------------------------------------------------------------------------
// Kernel 2: vertical 35-tall max + mean, all registers, 16-row strips.
// Block = (image n, 16-row strip). Thread = one half2 column.
// 10 bricks of 5 t-rows (t rows r0-17 .. r0+28+pad); ring tb[7][5];
// output o' = 5(c-6)+m, emitted for c>=6 (last brick: m<1 -> o'=15).
// Fully unrolled -> static register indices. Last block reduces + writes out.
// ---------------------------------------------------------------------------
__global__ __launch_bounds__(256) void vpass_kernel(float* __restrict__ out) {
    const int bx = blockIdx.x;
    const int n  = bx >> 5;
    const int st = bx & 31;
    const int r0 = st << 4;
    const int tid = threadIdx.x;

    const unsigned* base = (const unsigned*)(g_hmax + (size_t)n * HW);
    const int rbase = r0 - 17;

    unsigned s[9];
    unsigned tb[7][5];
    float acc = 0.0f;

    #pragma unroll
    for (int i = 0; i < 4; i++) {
        const int row = rbase + i;
        s[i] = ((unsigned)row < H) ? base[row * 256 + tid] : NEG2;
    }

    #pragma unroll
    for (int c = 0; c < 10; c++) {
        #pragma unroll
        for (int i = 4; i < 9; i++) {
            const int row = rbase + 5 * c + i;
            s[i] = ((unsigned)row < H) ? base[row * 256 + tid] : NEG2;
        }
        // all 5 windows share s[4]: prefix down, suffix up
        const unsigned pre3 = hmax2u(s[4], s[3]);
        const unsigned pre2 = hmax2u(pre3, s[2]);
        const unsigned pre1 = hmax2u(pre2, s[1]);
        const unsigned pre0 = hmax2u(pre1, s[0]);
        const unsigned suf5 = hmax2u(s[4], s[5]);
        const unsigned suf6 = hmax2u(suf5, s[6]);
        const unsigned suf7 = hmax2u(suf6, s[7]);
        const unsigned suf8 = hmax2u(suf7, s[8]);
        unsigned* t = tb[c % 7];
        t[0] = pre0;
        t[1] = hmax2u(pre1, suf5);
        t[2] = hmax2u(pre2, suf6);
        t[3] = hmax2u(pre3, suf7);
        t[4] = suf8;

        if (c >= 6) {
            #pragma unroll
            for (int m = 0; m < 5; m++) {
                if (c < 9 || m < 1) {           // last brick emits o'=15 only
                    unsigned v = tb[0][m];
                    v = hmax2u(v, tb[1][m]);
                    v = hmax2u(v, tb[2][m]);
                    v = hmax2u(v, tb[3][m]);
                    v = hmax2u(v, tb[4][m]);
                    v = hmax2u(v, tb[5][m]);
                    v = hmax2u(v, tb[6][m]);
                    const float2 f = __half22float2(*reinterpret_cast<__half2*>(&v));
                    acc += fabsf(f.x) + fabsf(f.y);
                }
            }
        }
        s[0] = s[5]; s[1] = s[6]; s[2] = s[7]; s[3] = s[8];
    }

    // block reduction 256 -> 1
    __shared__ float red[8];
    const int lane = tid & 31;
    #pragma unroll
    for (int off = 16; off; off >>= 1)
        acc += __shfl_down_sync(0xffffffffu, acc, off);
    if (lane == 0) red[tid >> 5] = acc;
    __syncthreads();
    if (tid < 8) {
        float v = red[tid];
        #pragma unroll
        for (int off = 4; off; off >>= 1)
            v += __shfl_down_sync(0xffu, v, off);
        if (tid == 0) g_partial[bx] = v;
    }

    // last block: deterministic final reduce + write
    __shared__ bool is_last;
    if (tid == 0) {
        __threadfence();
        is_last = (atomicAdd(&g_count, 1) == VBLK - 1);
    }
    __syncthreads();
    if (is_last) {
        __threadfence();
        float v = g_partial[tid]        + g_partial[tid + 256]
                + g_partial[tid + 512]  + g_partial[tid + 768];
        #pragma unroll
        for (int off = 16; off; off >>= 1)
            v += __shfl_down_sync(0xffffffffu, v, off);
        if (lane == 0) red[tid >> 5] = v;
        __syncthreads();
        if (tid < 8) {
            float x = red[tid];
            #pragma unroll
            for (int off = 4; off; off >>= 1)
                x += __shfl_down_sync(0xffu, x, off);
            if (tid == 0) {
                out[0] = x * (1.0f / ((float)NIMG * (float)HW));
                g_count = 0;   // reset for graph replay
            }
        }
    }
}

// ---------------------------------------------------------------------------
extern "C" void kernel_launch(void* const* d_in, const int* in_sizes, int n_in,
                              void* d_out, int out_size) {
    const float* img = (const float*)d_in[0];
    float* out = (float*)d_out;

    hpass_kernel<<<NIMG * H, 128>>>(img);
    vpass_kernel<<<VBLK, 256>>>(out);
}